// round 16
// baseline (speedup 1.0000x reference)
#include <cuda_runtime.h>
#include <cuda_bf16.h>
#include <cuda_fp16.h>
#include <cstdint>

// Problem constants
#define NN 100000
#define CC 128
#define HH 8
#define DD 16
#define EE 640000

// -------- device scratch (static; no runtime allocation allowed) --------
__device__ __half g_qh[NN * CC];
__device__ __half g_kh[NN * CC];
__device__ __half g_vh[NN * CC];
__device__ __half g_acch[NN * CC];
__device__ int    g_hist[NN];
__device__ int    g_cursor[NN];
__device__ int    g_rowptr[NN + 1];
__device__ int    g_ecol[EE];

// Pre-converted weights: bf16 hi/lo, row-major [4][128*128]
__device__ __nv_bfloat16 g_whi[4][CC * CC];
__device__ __nv_bfloat16 g_wlo[4][CC * CC];

#define SCAN_CHUNK 1024
#define SCAN_BLOCKS ((NN + SCAN_CHUNK - 1) / SCAN_CHUNK)   // 98
__device__ int g_bsum[SCAN_BLOCKS];
__device__ int g_boff[SCAN_BLOCKS];

#define GATHER_BLOCKS 1024
#define GATHER_THREADS 256
#define TOTAL_WARPS (GATHER_BLOCKS * GATHER_THREADS / 32)   // 8192
__device__ float g_partial[TOTAL_WARPS * HH];
__device__ float g_inv_denom[HH];
__device__ int   g_is32;             // 1 if edge_index is int32, 0 if int64

// fp16 quad <-> float4 helpers
__device__ __forceinline__ float4 half4_to_float4(uint2 u) {
    float2 a = __half22float2(*(__half2*)&u.x);
    float2 b = __half22float2(*(__half2*)&u.y);
    return make_float4(a.x, a.y, b.x, b.y);
}
__device__ __forceinline__ uint2 float4_to_half4(float4 v) {
    uint2 u;
    *(__half2*)&u.x = __floats2half2_rn(v.x, v.y);
    *(__half2*)&u.y = __floats2half2_rn(v.z, v.w);
    return u;
}

// ======================================================================
// Detect edge_index dtype (int32 vs int64)
// ======================================================================
__global__ void detect_kernel(const int* __restrict__ ei_words)
{
    int any = 0;
    #pragma unroll
    for (int i = 0; i < 64; i++)
        any |= ei_words[2 * i + 1];
    g_is32 = (any != 0) ? 1 : 0;
}

__device__ __forceinline__ void load_edge(const void* ei, int is32, int e,
                                          int& row, int& col)
{
    if (is32) {
        row = ((const int*)ei)[e];
        col = ((const int*)ei)[EE + e];
    } else {
        row = (int)((const long long*)ei)[e];
        col = (int)((const long long*)ei)[EE + e];
    }
    if ((unsigned)row >= NN) row = 0;
    if ((unsigned)col >= NN) col = 0;
}

// ======================================================================
// Pre-convert all 4 weight matrices to bf16 hi/lo (runs once per launch)
// ======================================================================
__global__ __launch_bounds__(256) void convw_kernel(
    const float* __restrict__ Wq, const float* __restrict__ Wk,
    const float* __restrict__ Wv, const float* __restrict__ Wo)
{
    const int i = blockIdx.x * blockDim.x + threadIdx.x;
    if (i >= CC * CC) return;
    const float* Ws[4] = {Wq, Wk, Wv, Wo};
    #pragma unroll
    for (int w = 0; w < 4; w++) {
        float x = Ws[w][i];
        __nv_bfloat16 h = __float2bfloat16(x);
        g_whi[w][i] = h;
        g_wlo[w][i] = __float2bfloat16(x - __bfloat162float(h));
    }
}

// ======================================================================
// CSR build: memset(hist) -> count -> scan(3-phase) -> fill
// ======================================================================
__global__ void count_kernel(const void* __restrict__ ei)
{
    const int is32 = g_is32;
    for (int e = blockIdx.x * blockDim.x + threadIdx.x; e < EE;
         e += gridDim.x * blockDim.x) {
        int row, col;
        load_edge(ei, is32, e, row, col);
        atomicAdd(&g_hist[row], 1);
    }
}

__global__ __launch_bounds__(256) void scan1_kernel()
{
    __shared__ int sh[256];
    const int b = blockIdx.x;
    const int t = threadIdx.x;
    const int base = b * SCAN_CHUNK + t * 4;
    int v[4];
    int s = 0;
    #pragma unroll
    for (int j = 0; j < 4; j++) {
        int idx = base + j;
        v[j] = (idx < NN) ? g_hist[idx] : 0;
        s += v[j];
    }
    sh[t] = s;
    __syncthreads();
    #pragma unroll
    for (int off = 1; off < 256; off <<= 1) {
        int x = (t >= off) ? sh[t - off] : 0;
        __syncthreads();
        sh[t] += x;
        __syncthreads();
    }
    int excl = (t == 0) ? 0 : sh[t - 1];
    #pragma unroll
    for (int j = 0; j < 4; j++) {
        int idx = base + j;
        if (idx < NN) g_rowptr[idx] = excl;
        excl += v[j];
    }
    if (t == 255) g_bsum[b] = sh[255];
}

__global__ __launch_bounds__(128) void scan2_kernel()
{
    __shared__ int sh[128];
    const int t = threadIdx.x;
    sh[t] = (t < SCAN_BLOCKS) ? g_bsum[t] : 0;
    __syncthreads();
    #pragma unroll
    for (int off = 1; off < 128; off <<= 1) {
        int x = (t >= off) ? sh[t - off] : 0;
        __syncthreads();
        sh[t] += x;
        __syncthreads();
    }
    if (t < SCAN_BLOCKS) g_boff[t] = (t == 0) ? 0 : sh[t - 1];
    if (t == 127) g_rowptr[NN] = sh[127];
}

// Phase 3: add chunk offsets; also seed cursor = rowptr for fill
__global__ __launch_bounds__(256) void scan3_kernel()
{
    const int b = blockIdx.x;
    const int off = g_boff[b];
    const int base = b * SCAN_CHUNK + threadIdx.x * 4;
    #pragma unroll
    for (int j = 0; j < 4; j++) {
        int idx = base + j;
        if (idx < NN) {
            int p = g_rowptr[idx] + off;
            g_rowptr[idx] = p;
            g_cursor[idx] = p;
        }
    }
}

__global__ void fill_kernel(const void* __restrict__ ei)
{
    const int is32 = g_is32;
    for (int e = blockIdx.x * blockDim.x + threadIdx.x; e < EE;
         e += gridDim.x * blockDim.x) {
        int row, col;
        load_edge(ei, is32, e, row, col);
        int slot = atomicAdd(&g_cursor[row], 1);
        g_ecol[slot] = col;
    }
}

// ======================================================================
// mma.sync helpers
// ======================================================================
__device__ __forceinline__ uint32_t smem_u32(const void* p) {
    uint32_t a;
    asm("{ .reg .u64 t; cvta.to.shared.u64 t, %1; cvt.u32.u64 %0, t; }"
        : "=r"(a) : "l"(p));
    return a;
}
__device__ __forceinline__ void ldsm_x4(uint32_t addr, uint32_t& r0, uint32_t& r1,
                                        uint32_t& r2, uint32_t& r3) {
    asm volatile("ldmatrix.sync.aligned.m8n8.x4.shared.b16 {%0,%1,%2,%3}, [%4];"
                 : "=r"(r0), "=r"(r1), "=r"(r2), "=r"(r3) : "r"(addr));
}
__device__ __forceinline__ void ldsm_x2(uint32_t addr, uint32_t& r0, uint32_t& r1) {
    asm volatile("ldmatrix.sync.aligned.m8n8.x2.shared.b16 {%0,%1}, [%2];"
                 : "=r"(r0), "=r"(r1) : "r"(addr));
}
__device__ __forceinline__ void mma16816(float* c, const uint32_t* a,
                                         const uint32_t* b) {
    asm volatile(
        "mma.sync.aligned.m16n8k16.row.col.f32.bf16.bf16.f32 "
        "{%0,%1,%2,%3}, {%4,%5,%6,%7}, {%8,%9}, {%0,%1,%2,%3};"
        : "+f"(c[0]), "+f"(c[1]), "+f"(c[2]), "+f"(c[3])
        : "r"(a[0]), "r"(a[1]), "r"(a[2]), "r"(a[3]), "r"(b[0]), "r"(b[1]));
}

// ======================================================================
// GEMM building blocks (bf16 2-way split, fp32 accumulate)
// Tile: 128 rows x 128 cols, 256 threads (8 warps, 2x4).
// ======================================================================
#define TSTRIDE 136
#define A_TILE_ELEMS (128 * TSTRIDE)
#define W_TILE_ELEMS (128 * TSTRIDE)
#define SM_TOTAL ((2 * A_TILE_ELEMS + 2 * W_TILE_ELEMS) * 2)

__device__ __forceinline__ void split_store(__nv_bfloat16* hi, __nv_bfloat16* lo,
                                            int off, float4 v) {
    #pragma unroll
    for (int j = 0; j < 4; j++) {
        float x = (j == 0) ? v.x : (j == 1) ? v.y : (j == 2) ? v.z : v.w;
        __nv_bfloat16 h = __float2bfloat16(x);
        hi[off + j] = h;
        lo[off + j] = __float2bfloat16(x - __bfloat162float(h));
    }
}

__device__ __forceinline__ void copy_w(const __nv_bfloat16* __restrict__ whi,
                                       const __nv_bfloat16* __restrict__ wlo,
                                       __nv_bfloat16* w_hi, __nv_bfloat16* w_lo,
                                       int tid) {
    #pragma unroll
    for (int i = 0; i < 8; i++) {
        int f  = tid + i * 256;      // 8-elem group index 0..2047
        int r  = f >> 4;             // 0..127
        int c8 = f & 15;             // 0..15
        uint4 h = ((const uint4*)whi)[f];
        uint4 l = ((const uint4*)wlo)[f];
        *(uint4*)&w_hi[r * TSTRIDE + c8 * 8] = h;
        *(uint4*)&w_lo[r * TSTRIDE + c8 * 8] = l;
    }
}

// Load + convert 128-row A tile from fp32 source
__device__ __forceinline__ void conv_a128(const float* __restrict__ A,
                                          __nv_bfloat16* a_hi, __nv_bfloat16* a_lo,
                                          int row0, int tid) {
    #pragma unroll
    for (int i = 0; i < 16; i++) {
        int f  = tid + i * 256;     // float4 index 0..4095
        int r  = f >> 5;            // 0..127
        int c4 = f & 31;
        float4 va = make_float4(0.f, 0.f, 0.f, 0.f);
        int gr = row0 + r;
        if (gr < NN) va = ((const float4*)A)[gr * 32 + c4];
        split_store(a_hi, a_lo, r * TSTRIDE + c4 * 4, va);
    }
}

// Load + convert 128-row A tile from fp16 source with per-head column scale
__device__ __forceinline__ void conv_a128h(const __half* __restrict__ A,
                                           const float* __restrict__ colscale,
                                           __nv_bfloat16* a_hi, __nv_bfloat16* a_lo,
                                           int row0, int tid) {
    const uint2* A4 = (const uint2*)A;   // 4 halfs per element
    #pragma unroll
    for (int i = 0; i < 16; i++) {
        int f  = tid + i * 256;     // quad index 0..4095
        int r  = f >> 5;            // 0..127
        int c4 = f & 31;
        float4 va = make_float4(0.f, 0.f, 0.f, 0.f);
        int gr = row0 + r;
        if (gr < NN) va = half4_to_float4(__ldg(&A4[gr * 32 + c4]));
        float sc = __ldg(&colscale[c4 >> 2]);   // head = (c4*4)/16
        va.x *= sc; va.y *= sc; va.z *= sc; va.w *= sc;
        split_store(a_hi, a_lo, r * TSTRIDE + c4 * 4, va);
    }
}

// MMA compute + epilogue, 128x128 tile, warp grid 2(m) x 4(n).
// Writes fp32 (out) or fp16 (out_h); exactly one is non-null.
__device__ __forceinline__ void mma_compute_store(
    const __nv_bfloat16* a_hi, const __nv_bfloat16* a_lo,
    const __nv_bfloat16* w_hi, const __nv_bfloat16* w_lo,
    const float* __restrict__ bias,
    float* __restrict__ out, __half* __restrict__ out_h,
    int row0, int wid, int lane)
{
    const int m_warp = (wid >> 2) * 64;   // 0 or 64
    const int n_warp = (wid & 3) * 32;    // 0,32,64,96
    const uint32_t aH_base = smem_u32(a_hi);
    const uint32_t aL_base = smem_u32(a_lo);
    const uint32_t wH_base = smem_u32(w_hi);
    const uint32_t wL_base = smem_u32(w_lo);
    const uint32_t a_lane_off =
        (uint32_t)(((lane & 15)) * TSTRIDE + 8 * (lane >> 4)) * 2;
    const uint32_t b_lane_off =
        (uint32_t)(((lane & 7)) * TSTRIDE + 8 * ((lane >> 3) & 1)) * 2;

    float acc[4][4][4];
    #pragma unroll
    for (int mt = 0; mt < 4; mt++)
        #pragma unroll
        for (int nt = 0; nt < 4; nt++)
            #pragma unroll
            for (int j = 0; j < 4; j++) acc[mt][nt][j] = 0.f;

    #pragma unroll
    for (int kt = 0; kt < 8; kt++) {
        const uint32_t koff = kt * 32;
        uint32_t aH[4][4], aL[4][4];
        #pragma unroll
        for (int mt = 0; mt < 4; mt++) {
            uint32_t ra = (uint32_t)((m_warp + mt * 16) * TSTRIDE * 2) + a_lane_off + koff;
            ldsm_x4(aH_base + ra, aH[mt][0], aH[mt][1], aH[mt][2], aH[mt][3]);
            ldsm_x4(aL_base + ra, aL[mt][0], aL[mt][1], aL[mt][2], aL[mt][3]);
        }
        #pragma unroll
        for (int nt = 0; nt < 4; nt++) {
            uint32_t rb = (uint32_t)((n_warp + nt * 8) * TSTRIDE * 2) + b_lane_off + koff;
            uint32_t bH[2], bL[2];
            ldsm_x2(wH_base + rb, bH[0], bH[1]);
            ldsm_x2(wL_base + rb, bL[0], bL[1]);
            #pragma unroll
            for (int mt = 0; mt < 4; mt++) {
                mma16816(acc[mt][nt], aH[mt], bH);
                mma16816(acc[mt][nt], aH[mt], bL);
                mma16816(acc[mt][nt], aL[mt], bH);
            }
        }
    }

    const int qrow = lane >> 2;
    const int qcol = (lane & 3) * 2;
    #pragma unroll
    for (int mt = 0; mt < 4; mt++) {
        #pragma unroll
        for (int half = 0; half < 2; half++) {
            int grow = row0 + m_warp + mt * 16 + qrow + half * 8;
            if (grow < NN) {
                #pragma unroll
                for (int nt = 0; nt < 4; nt++) {
                    int col = n_warp + nt * 8 + qcol;
                    float ox = acc[mt][nt][half * 2 + 0] + __ldg(&bias[col]);
                    float oy = acc[mt][nt][half * 2 + 1] + __ldg(&bias[col + 1]);
                    if (out) {
                        *(float2*)&out[grow * 128 + col] = make_float2(ox, oy);
                    } else {
                        *(__half2*)&out_h[grow * 128 + col] =
                            __floats2half2_rn(ox, oy);
                    }
                }
            }
        }
    }
}

// Fused Q/K/V GEMM: all outputs fp16 (consumed only by gather)
__global__ __launch_bounds__(256) void gemm_qkv_kernel(
    const float* __restrict__ A,
    const float* __restrict__ bq, const float* __restrict__ bk,
    const float* __restrict__ bv)
{
    extern __shared__ __nv_bfloat16 smem[];
    __nv_bfloat16* a_hi = smem;
    __nv_bfloat16* a_lo = smem + A_TILE_ELEMS;
    __nv_bfloat16* w_hi = smem + 2 * A_TILE_ELEMS;
    __nv_bfloat16* w_lo = smem + 2 * A_TILE_ELEMS + W_TILE_ELEMS;

    const int tid  = threadIdx.x;
    const int wid  = tid >> 5;
    const int lane = tid & 31;
    const int row0 = blockIdx.x * 128;

    conv_a128(A, a_hi, a_lo, row0, tid);

    __half* outs[3] = {g_qh, g_kh, g_vh};
    const float* bs[3] = {bq, bk, bv};
    #pragma unroll 1
    for (int w = 0; w < 3; w++) {
        copy_w(g_whi[w], g_wlo[w], w_hi, w_lo, tid);
        __syncthreads();
        mma_compute_store(a_hi, a_lo, w_hi, w_lo, bs[w], (float*)0, outs[w],
                          row0, wid, lane);
        __syncthreads();
    }
}

// Final Wo GEMM: fp16 acc input with per-head column scale
__global__ __launch_bounds__(256) void gemm_mma_kernel(
    const float* __restrict__ bias,
    float* __restrict__ out,
    const float* __restrict__ colscale)
{
    extern __shared__ __nv_bfloat16 smem[];
    __nv_bfloat16* a_hi = smem;
    __nv_bfloat16* a_lo = smem + A_TILE_ELEMS;
    __nv_bfloat16* w_hi = smem + 2 * A_TILE_ELEMS;
    __nv_bfloat16* w_lo = smem + 2 * A_TILE_ELEMS + W_TILE_ELEMS;

    const int tid  = threadIdx.x;
    const int wid  = tid >> 5;
    const int lane = tid & 31;
    const int row0 = blockIdx.x * 128;

    conv_a128h(g_acch, colscale, a_hi, a_lo, row0, tid);
    copy_w(g_whi[3], g_wlo[3], w_hi, w_lo, tid);
    __syncthreads();
    mma_compute_store(a_hi, a_lo, w_hi, w_lo, bias, out, (__half*)0,
                      row0, wid, lane);
}

// ======================================================================
// Gather: one warp per node; 2 edges in flight; q/k/v fp16, acc fp16 out.
// Lane l covers channels [4l, 4l+4): 4 halfs = one uint2 (8B).
// ======================================================================
__global__ __launch_bounds__(GATHER_THREADS) void gather_kernel()
{
    const int lane = threadIdx.x & 31;
    const int warp = (blockIdx.x * blockDim.x + threadIdx.x) >> 5;
    const int h = lane >> 2;
    float hsum = 0.f;
    const uint2* qh = (const uint2*)g_qh;
    const uint2* kh = (const uint2*)g_kh;
    const uint2* vh = (const uint2*)g_vh;
    uint2* acch = (uint2*)g_acch;

    for (int n = warp; n < NN; n += TOTAL_WARPS) {
        float4 q4 = half4_to_float4(__ldg(&qh[n * 32 + lane]));
        float4 a = make_float4(0.f, 0.f, 0.f, 0.f);
        const int beg = g_rowptr[n];
        const int end = g_rowptr[n + 1];
        int j = beg;
        for (; j + 1 < end; j += 2) {
            int c0 = __ldg(&g_ecol[j]);
            int c1 = __ldg(&g_ecol[j + 1]);
            float4 k0 = half4_to_float4(__ldg(&kh[c0 * 32 + lane]));
            float4 v0 = half4_to_float4(__ldg(&vh[c0 * 32 + lane]));
            float4 k1 = half4_to_float4(__ldg(&kh[c1 * 32 + lane]));
            float4 v1 = half4_to_float4(__ldg(&vh[c1 * 32 + lane]));
            float p0 = q4.x * k0.x + q4.y * k0.y + q4.z * k0.z + q4.w * k0.w;
            float p1 = q4.x * k1.x + q4.y * k1.y + q4.z * k1.z + q4.w * k1.w;
            p0 += __shfl_xor_sync(0xFFFFFFFFu, p0, 1);
            p1 += __shfl_xor_sync(0xFFFFFFFFu, p1, 1);
            p0 += __shfl_xor_sync(0xFFFFFFFFu, p0, 2);
            p1 += __shfl_xor_sync(0xFFFFFFFFu, p1, 2);
            float w0 = __expf(p0 * 0.25f);
            float w1 = __expf(p1 * 0.25f);
            if ((lane & 3) == 0) hsum += w0 + w1;
            a.x += w0 * v0.x + w1 * v1.x;
            a.y += w0 * v0.y + w1 * v1.y;
            a.z += w0 * v0.z + w1 * v1.z;
            a.w += w0 * v0.w + w1 * v1.w;
        }
        if (j < end) {
            int c0 = __ldg(&g_ecol[j]);
            float4 k0 = half4_to_float4(__ldg(&kh[c0 * 32 + lane]));
            float4 v0 = half4_to_float4(__ldg(&vh[c0 * 32 + lane]));
            float p0 = q4.x * k0.x + q4.y * k0.y + q4.z * k0.z + q4.w * k0.w;
            p0 += __shfl_xor_sync(0xFFFFFFFFu, p0, 1);
            p0 += __shfl_xor_sync(0xFFFFFFFFu, p0, 2);
            float w0 = __expf(p0 * 0.25f);
            if ((lane & 3) == 0) hsum += w0;
            a.x += w0 * v0.x;
            a.y += w0 * v0.y;
            a.z += w0 * v0.z;
            a.w += w0 * v0.w;
        }
        acch[n * 32 + lane] = float4_to_half4(a);
    }
    if ((lane & 3) == 0) g_partial[warp * 8 + h] = hsum;
}

// ======================================================================
// Deterministic denominator reduction: 1 block, fixed summation order.
// ======================================================================
__global__ void denom_kernel()
{
    __shared__ float sh[256];
    const int t = threadIdx.x;
    const int h = t & 7;
    const int i0 = t >> 3;
    float s = 0.f;
    for (int i = i0; i < TOTAL_WARPS; i += 32)
        s += g_partial[i * 8 + h];
    sh[t] = s;
    __syncthreads();
    if (t < 8) {
        float tot = 0.f;
        #pragma unroll
        for (int j = 0; j < 32; j++) tot += sh[t + j * 8];
        g_inv_denom[t] = 1.0f / tot;
    }
}

// ======================================================================
// kernel_launch — branch A (convw+QKV) on stream 0; branch B (detect+CSR)
// on side stream; join before gather.
// ======================================================================
extern "C" void kernel_launch(void* const* d_in, const int* in_sizes, int n_in,
                              void* d_out, int out_size)
{
    const float* feat = (const float*)d_in[0];
    const void*  ei   = d_in[1];
    const float* Wq   = (const float*)d_in[2];
    const float* bq   = (const float*)d_in[3];
    const float* Wk   = (const float*)d_in[4];
    const float* bk   = (const float*)d_in[5];
    const float* Wv   = (const float*)d_in[6];
    const float* bv   = (const float*)d_in[7];
    const float* Wo   = (const float*)d_in[8];
    const float* bo   = (const float*)d_in[9];
    float* out = (float*)d_out;

    cudaFuncSetAttribute(gemm_qkv_kernel,
                         cudaFuncAttributeMaxDynamicSharedMemorySize, SM_TOTAL);
    cudaFuncSetAttribute(gemm_mma_kernel,
                         cudaFuncAttributeMaxDynamicSharedMemorySize, SM_TOTAL);

    float* inv;  cudaGetSymbolAddress((void**)&inv,  g_inv_denom);
    int*   hist; cudaGetSymbolAddress((void**)&hist, g_hist);

    const int gemm_blocks = (NN + 127) / 128;  // 782

    // Side stream + fork/join events (host objects only).
    cudaStream_t s2;
    cudaStreamCreateWithFlags(&s2, cudaStreamNonBlocking);
    cudaEvent_t ev_fork, ev_join;
    cudaEventCreateWithFlags(&ev_fork, cudaEventDisableTiming);
    cudaEventCreateWithFlags(&ev_join, cudaEventDisableTiming);

    // Fork: s2 must be downstream of any prior work on stream 0.
    cudaEventRecord(ev_fork, 0);
    cudaStreamWaitEvent(s2, ev_fork, 0);

    // ---- branch A (stream 0): weight convert + QKV GEMM ----
    convw_kernel<<<64, 256>>>(Wq, Wk, Wv, Wo);
    gemm_qkv_kernel<<<gemm_blocks, 256, SM_TOTAL>>>(feat, bq, bk, bv);

    // ---- branch B (stream s2): dtype detect + CSR build ----
    detect_kernel<<<1, 1, 0, s2>>>((const int*)ei);
    cudaMemsetAsync(hist, 0, NN * sizeof(int), s2);
    count_kernel<<<1280, 256, 0, s2>>>(ei);
    scan1_kernel<<<SCAN_BLOCKS, 256, 0, s2>>>();
    scan2_kernel<<<1, 128, 0, s2>>>();
    scan3_kernel<<<SCAN_BLOCKS, 256, 0, s2>>>();
    fill_kernel<<<1280, 256, 0, s2>>>(ei);
    cudaEventRecord(ev_join, s2);

    // ---- join, then attention + output projection on stream 0 ----
    cudaStreamWaitEvent(0, ev_join, 0);
    gather_kernel<<<GATHER_BLOCKS, GATHER_THREADS>>>();
    denom_kernel<<<1, 256>>>();
    gemm_mma_kernel<<<gemm_blocks, 256, SM_TOTAL>>>(bo, out, inv);
}

// round 17
// speedup vs baseline: 1.0120x; 1.0120x over previous
#include <cuda_runtime.h>
#include <cuda_bf16.h>
#include <cuda_fp16.h>
#include <cstdint>

// Problem constants
#define NN 100000
#define CC 128
#define HH 8
#define DD 16
#define EE 640000

// -------- device scratch (static; no runtime allocation allowed) --------
__device__ float  g_q[NN * CC];
__device__ __half g_kvh[NN * 2 * CC];   // interleaved: node*256 + lane*8 = {k4, v4}
__device__ float  g_acc[NN * CC];
__device__ int    g_hist[NN];
__device__ int    g_cursor[NN];
__device__ int    g_rowptr[NN + 1];
__device__ int    g_ecol[EE];

// Pre-converted weights: bf16 hi/lo, row-major [4][128*128]
__device__ __nv_bfloat16 g_whi[4][CC * CC];
__device__ __nv_bfloat16 g_wlo[4][CC * CC];

#define SCAN_CHUNK 1024
#define SCAN_BLOCKS ((NN + SCAN_CHUNK - 1) / SCAN_CHUNK)   // 98
__device__ int g_bsum[SCAN_BLOCKS];
__device__ int g_boff[SCAN_BLOCKS];

#define GATHER_BLOCKS 1024
#define GATHER_THREADS 256
#define TOTAL_WARPS (GATHER_BLOCKS * GATHER_THREADS / 32)   // 8192
__device__ float g_partial[TOTAL_WARPS * HH];
__device__ float g_inv_denom[HH];
__device__ int   g_is32;             // 1 if edge_index is int32, 0 if int64

// fp16 quad -> float4 helper
__device__ __forceinline__ float4 half4_to_float4(uint32_t lo, uint32_t hi) {
    float2 a = __half22float2(*(__half2*)&lo);
    float2 b = __half22float2(*(__half2*)&hi);
    return make_float4(a.x, a.y, b.x, b.y);
}

// ======================================================================
// Detect edge_index dtype (int32 vs int64)
// ======================================================================
__global__ void detect_kernel(const int* __restrict__ ei_words)
{
    int any = 0;
    #pragma unroll
    for (int i = 0; i < 64; i++)
        any |= ei_words[2 * i + 1];
    g_is32 = (any != 0) ? 1 : 0;
}

__device__ __forceinline__ void load_edge(const void* ei, int is32, int e,
                                          int& row, int& col)
{
    if (is32) {
        row = ((const int*)ei)[e];
        col = ((const int*)ei)[EE + e];
    } else {
        row = (int)((const long long*)ei)[e];
        col = (int)((const long long*)ei)[EE + e];
    }
    if ((unsigned)row >= NN) row = 0;
    if ((unsigned)col >= NN) col = 0;
}

// ======================================================================
// Pre-convert all 4 weight matrices to bf16 hi/lo (runs once per launch)
// ======================================================================
__global__ __launch_bounds__(256) void convw_kernel(
    const float* __restrict__ Wq, const float* __restrict__ Wk,
    const float* __restrict__ Wv, const float* __restrict__ Wo)
{
    const int i = blockIdx.x * blockDim.x + threadIdx.x;
    if (i >= CC * CC) return;
    const float* Ws[4] = {Wq, Wk, Wv, Wo};
    #pragma unroll
    for (int w = 0; w < 4; w++) {
        float x = Ws[w][i];
        __nv_bfloat16 h = __float2bfloat16(x);
        g_whi[w][i] = h;
        g_wlo[w][i] = __float2bfloat16(x - __bfloat162float(h));
    }
}

// ======================================================================
// CSR build: memset(hist) -> count -> scan(3-phase) -> fill
// ======================================================================
__global__ void count_kernel(const void* __restrict__ ei)
{
    const int is32 = g_is32;
    for (int e = blockIdx.x * blockDim.x + threadIdx.x; e < EE;
         e += gridDim.x * blockDim.x) {
        int row, col;
        load_edge(ei, is32, e, row, col);
        atomicAdd(&g_hist[row], 1);
    }
}

__global__ __launch_bounds__(256) void scan1_kernel()
{
    __shared__ int sh[256];
    const int b = blockIdx.x;
    const int t = threadIdx.x;
    const int base = b * SCAN_CHUNK + t * 4;
    int v[4];
    int s = 0;
    #pragma unroll
    for (int j = 0; j < 4; j++) {
        int idx = base + j;
        v[j] = (idx < NN) ? g_hist[idx] : 0;
        s += v[j];
    }
    sh[t] = s;
    __syncthreads();
    #pragma unroll
    for (int off = 1; off < 256; off <<= 1) {
        int x = (t >= off) ? sh[t - off] : 0;
        __syncthreads();
        sh[t] += x;
        __syncthreads();
    }
    int excl = (t == 0) ? 0 : sh[t - 1];
    #pragma unroll
    for (int j = 0; j < 4; j++) {
        int idx = base + j;
        if (idx < NN) g_rowptr[idx] = excl;
        excl += v[j];
    }
    if (t == 255) g_bsum[b] = sh[255];
}

__global__ __launch_bounds__(128) void scan2_kernel()
{
    __shared__ int sh[128];
    const int t = threadIdx.x;
    sh[t] = (t < SCAN_BLOCKS) ? g_bsum[t] : 0;
    __syncthreads();
    #pragma unroll
    for (int off = 1; off < 128; off <<= 1) {
        int x = (t >= off) ? sh[t - off] : 0;
        __syncthreads();
        sh[t] += x;
        __syncthreads();
    }
    if (t < SCAN_BLOCKS) g_boff[t] = (t == 0) ? 0 : sh[t - 1];
    if (t == 127) g_rowptr[NN] = sh[127];
}

// Phase 3: add chunk offsets; also seed cursor = rowptr for fill
__global__ __launch_bounds__(256) void scan3_kernel()
{
    const int b = blockIdx.x;
    const int off = g_boff[b];
    const int base = b * SCAN_CHUNK + threadIdx.x * 4;
    #pragma unroll
    for (int j = 0; j < 4; j++) {
        int idx = base + j;
        if (idx < NN) {
            int p = g_rowptr[idx] + off;
            g_rowptr[idx] = p;
            g_cursor[idx] = p;
        }
    }
}

__global__ void fill_kernel(const void* __restrict__ ei)
{
    const int is32 = g_is32;
    for (int e = blockIdx.x * blockDim.x + threadIdx.x; e < EE;
         e += gridDim.x * blockDim.x) {
        int row, col;
        load_edge(ei, is32, e, row, col);
        int slot = atomicAdd(&g_cursor[row], 1);
        g_ecol[slot] = col;
    }
}

// ======================================================================
// mma.sync helpers
// ======================================================================
__device__ __forceinline__ uint32_t smem_u32(const void* p) {
    uint32_t a;
    asm("{ .reg .u64 t; cvta.to.shared.u64 t, %1; cvt.u32.u64 %0, t; }"
        : "=r"(a) : "l"(p));
    return a;
}
__device__ __forceinline__ void ldsm_x4(uint32_t addr, uint32_t& r0, uint32_t& r1,
                                        uint32_t& r2, uint32_t& r3) {
    asm volatile("ldmatrix.sync.aligned.m8n8.x4.shared.b16 {%0,%1,%2,%3}, [%4];"
                 : "=r"(r0), "=r"(r1), "=r"(r2), "=r"(r3) : "r"(addr));
}
__device__ __forceinline__ void ldsm_x2(uint32_t addr, uint32_t& r0, uint32_t& r1) {
    asm volatile("ldmatrix.sync.aligned.m8n8.x2.shared.b16 {%0,%1}, [%2];"
                 : "=r"(r0), "=r"(r1) : "r"(addr));
}
__device__ __forceinline__ void mma16816(float* c, const uint32_t* a,
                                         const uint32_t* b) {
    asm volatile(
        "mma.sync.aligned.m16n8k16.row.col.f32.bf16.bf16.f32 "
        "{%0,%1,%2,%3}, {%4,%5,%6,%7}, {%8,%9}, {%0,%1,%2,%3};"
        : "+f"(c[0]), "+f"(c[1]), "+f"(c[2]), "+f"(c[3])
        : "r"(a[0]), "r"(a[1]), "r"(a[2]), "r"(a[3]), "r"(b[0]), "r"(b[1]));
}

// ======================================================================
// GEMM building blocks (bf16 2-way split, fp32 accumulate)
// Tile: 128 rows x 128 cols, 256 threads (8 warps, 2x4).
// ======================================================================
#define TSTRIDE 136
#define A_TILE_ELEMS (128 * TSTRIDE)
#define W_TILE_ELEMS (128 * TSTRIDE)
#define SM_TOTAL ((2 * A_TILE_ELEMS + 2 * W_TILE_ELEMS) * 2)

__device__ __forceinline__ void split_store(__nv_bfloat16* hi, __nv_bfloat16* lo,
                                            int off, float4 v) {
    #pragma unroll
    for (int j = 0; j < 4; j++) {
        float x = (j == 0) ? v.x : (j == 1) ? v.y : (j == 2) ? v.z : v.w;
        __nv_bfloat16 h = __float2bfloat16(x);
        hi[off + j] = h;
        lo[off + j] = __float2bfloat16(x - __bfloat162float(h));
    }
}

__device__ __forceinline__ void copy_w(const __nv_bfloat16* __restrict__ whi,
                                       const __nv_bfloat16* __restrict__ wlo,
                                       __nv_bfloat16* w_hi, __nv_bfloat16* w_lo,
                                       int tid) {
    #pragma unroll
    for (int i = 0; i < 8; i++) {
        int f  = tid + i * 256;      // 8-elem group index 0..2047
        int r  = f >> 4;             // 0..127
        int c8 = f & 15;             // 0..15
        uint4 h = ((const uint4*)whi)[f];
        uint4 l = ((const uint4*)wlo)[f];
        *(uint4*)&w_hi[r * TSTRIDE + c8 * 8] = h;
        *(uint4*)&w_lo[r * TSTRIDE + c8 * 8] = l;
    }
}

// Load + convert 128-row A tile (guarded, optional per-head column scale)
__device__ __forceinline__ void conv_a128(const float* __restrict__ A,
                                          const float* __restrict__ colscale,
                                          __nv_bfloat16* a_hi, __nv_bfloat16* a_lo,
                                          int row0, int tid) {
    #pragma unroll
    for (int i = 0; i < 16; i++) {
        int f  = tid + i * 256;     // float4 index 0..4095
        int r  = f >> 5;            // 0..127
        int c4 = f & 31;
        float4 va = make_float4(0.f, 0.f, 0.f, 0.f);
        int gr = row0 + r;
        if (gr < NN) va = ((const float4*)A)[gr * 32 + c4];
        if (colscale) {
            float sc = __ldg(&colscale[c4 >> 2]);   // head = (c4*4)/16
            va.x *= sc; va.y *= sc; va.z *= sc; va.w *= sc;
        }
        split_store(a_hi, a_lo, r * TSTRIDE + c4 * 4, va);
    }
}

// MMA compute + epilogue, 128x128 tile, warp grid 2(m) x 4(n).
// out != 0  -> fp32 row-major [N,128]
// out == 0  -> fp16 interleaved kv: half index = row*256 + (col>>2)*8 + which*4 + (col&3)
__device__ __forceinline__ void mma_compute_store(
    const __nv_bfloat16* a_hi, const __nv_bfloat16* a_lo,
    const __nv_bfloat16* w_hi, const __nv_bfloat16* w_lo,
    const float* __restrict__ bias,
    float* __restrict__ out, __half* __restrict__ out_kv, int which,
    int row0, int wid, int lane)
{
    const int m_warp = (wid >> 2) * 64;   // 0 or 64
    const int n_warp = (wid & 3) * 32;    // 0,32,64,96
    const uint32_t aH_base = smem_u32(a_hi);
    const uint32_t aL_base = smem_u32(a_lo);
    const uint32_t wH_base = smem_u32(w_hi);
    const uint32_t wL_base = smem_u32(w_lo);
    const uint32_t a_lane_off =
        (uint32_t)(((lane & 15)) * TSTRIDE + 8 * (lane >> 4)) * 2;
    const uint32_t b_lane_off =
        (uint32_t)(((lane & 7)) * TSTRIDE + 8 * ((lane >> 3) & 1)) * 2;

    float acc[4][4][4];
    #pragma unroll
    for (int mt = 0; mt < 4; mt++)
        #pragma unroll
        for (int nt = 0; nt < 4; nt++)
            #pragma unroll
            for (int j = 0; j < 4; j++) acc[mt][nt][j] = 0.f;

    #pragma unroll
    for (int kt = 0; kt < 8; kt++) {
        const uint32_t koff = kt * 32;
        uint32_t aH[4][4], aL[4][4];
        #pragma unroll
        for (int mt = 0; mt < 4; mt++) {
            uint32_t ra = (uint32_t)((m_warp + mt * 16) * TSTRIDE * 2) + a_lane_off + koff;
            ldsm_x4(aH_base + ra, aH[mt][0], aH[mt][1], aH[mt][2], aH[mt][3]);
            ldsm_x4(aL_base + ra, aL[mt][0], aL[mt][1], aL[mt][2], aL[mt][3]);
        }
        #pragma unroll
        for (int nt = 0; nt < 4; nt++) {
            uint32_t rb = (uint32_t)((n_warp + nt * 8) * TSTRIDE * 2) + b_lane_off + koff;
            uint32_t bH[2], bL[2];
            ldsm_x2(wH_base + rb, bH[0], bH[1]);
            ldsm_x2(wL_base + rb, bL[0], bL[1]);
            #pragma unroll
            for (int mt = 0; mt < 4; mt++) {
                mma16816(acc[mt][nt], aH[mt], bH);
                mma16816(acc[mt][nt], aH[mt], bL);
                mma16816(acc[mt][nt], aL[mt], bH);
            }
        }
    }

    const int qrow = lane >> 2;
    const int qcol = (lane & 3) * 2;
    #pragma unroll
    for (int mt = 0; mt < 4; mt++) {
        #pragma unroll
        for (int half = 0; half < 2; half++) {
            int grow = row0 + m_warp + mt * 16 + qrow + half * 8;
            if (grow < NN) {
                #pragma unroll
                for (int nt = 0; nt < 4; nt++) {
                    int col = n_warp + nt * 8 + qcol;
                    float ox = acc[mt][nt][half * 2 + 0] + __ldg(&bias[col]);
                    float oy = acc[mt][nt][half * 2 + 1] + __ldg(&bias[col + 1]);
                    if (out) {
                        *(float2*)&out[grow * 128 + col] = make_float2(ox, oy);
                    } else {
                        int idx = grow * 256 + ((col >> 2) << 3) + (which << 2)
                                + (col & 3);
                        *(__half2*)&out_kv[idx] = __floats2half2_rn(ox, oy);
                    }
                }
            }
        }
    }
}

// Fused Q/K/V GEMM: q fp32; k/v fp16 interleaved into g_kvh
__global__ __launch_bounds__(256) void gemm_qkv_kernel(
    const float* __restrict__ A,
    const float* __restrict__ bq, const float* __restrict__ bk,
    const float* __restrict__ bv)
{
    extern __shared__ __nv_bfloat16 smem[];
    __nv_bfloat16* a_hi = smem;
    __nv_bfloat16* a_lo = smem + A_TILE_ELEMS;
    __nv_bfloat16* w_hi = smem + 2 * A_TILE_ELEMS;
    __nv_bfloat16* w_lo = smem + 2 * A_TILE_ELEMS + W_TILE_ELEMS;

    const int tid  = threadIdx.x;
    const int wid  = tid >> 5;
    const int lane = tid & 31;
    const int row0 = blockIdx.x * 128;

    conv_a128(A, (const float*)0, a_hi, a_lo, row0, tid);

    // w=0: Q (fp32)
    copy_w(g_whi[0], g_wlo[0], w_hi, w_lo, tid);
    __syncthreads();
    mma_compute_store(a_hi, a_lo, w_hi, w_lo, bq, g_q, (__half*)0, 0,
                      row0, wid, lane);
    __syncthreads();
    // w=1: K (fp16 kv slot 0)
    copy_w(g_whi[1], g_wlo[1], w_hi, w_lo, tid);
    __syncthreads();
    mma_compute_store(a_hi, a_lo, w_hi, w_lo, bk, (float*)0, g_kvh, 0,
                      row0, wid, lane);
    __syncthreads();
    // w=2: V (fp16 kv slot 1)
    copy_w(g_whi[2], g_wlo[2], w_hi, w_lo, tid);
    __syncthreads();
    mma_compute_store(a_hi, a_lo, w_hi, w_lo, bv, (float*)0, g_kvh, 1,
                      row0, wid, lane);
}

// Final Wo GEMM: per-head column scale on A, pre-converted W index 3
__global__ __launch_bounds__(256) void gemm_mma_kernel(
    const float* __restrict__ A,
    const float* __restrict__ bias,
    float* __restrict__ out,
    const float* __restrict__ colscale)
{
    extern __shared__ __nv_bfloat16 smem[];
    __nv_bfloat16* a_hi = smem;
    __nv_bfloat16* a_lo = smem + A_TILE_ELEMS;
    __nv_bfloat16* w_hi = smem + 2 * A_TILE_ELEMS;
    __nv_bfloat16* w_lo = smem + 2 * A_TILE_ELEMS + W_TILE_ELEMS;

    const int tid  = threadIdx.x;
    const int wid  = tid >> 5;
    const int lane = tid & 31;
    const int row0 = blockIdx.x * 128;

    conv_a128(A, colscale, a_hi, a_lo, row0, tid);
    copy_w(g_whi[3], g_wlo[3], w_hi, w_lo, tid);
    __syncthreads();
    mma_compute_store(a_hi, a_lo, w_hi, w_lo, bias, out, (__half*)0, 0,
                      row0, wid, lane);
}

// ======================================================================
// Gather: one warp per node; 2 edges in flight; ONE 16B kv load per edge
// per lane. Lane l covers channels [4l, 4l+4).
// ======================================================================
__global__ __launch_bounds__(GATHER_THREADS) void gather_kernel()
{
    const int lane = threadIdx.x & 31;
    const int warp = (blockIdx.x * blockDim.x + threadIdx.x) >> 5;
    const int h = lane >> 2;
    float hsum = 0.f;
    const uint4* kv = (const uint4*)g_kvh;   // 8 halfs per (node,lane)

    for (int n = warp; n < NN; n += TOTAL_WARPS) {
        float4 q4 = ((const float4*)g_q)[n * 32 + lane];
        float4 a = make_float4(0.f, 0.f, 0.f, 0.f);
        const int beg = g_rowptr[n];
        const int end = g_rowptr[n + 1];
        int j = beg;
        for (; j + 1 < end; j += 2) {
            int c0 = __ldg(&g_ecol[j]);
            int c1 = __ldg(&g_ecol[j + 1]);
            uint4 u0 = __ldg(&kv[c0 * 32 + lane]);
            uint4 u1 = __ldg(&kv[c1 * 32 + lane]);
            float4 k0 = half4_to_float4(u0.x, u0.y);
            float4 v0 = half4_to_float4(u0.z, u0.w);
            float4 k1 = half4_to_float4(u1.x, u1.y);
            float4 v1 = half4_to_float4(u1.z, u1.w);
            float p0 = q4.x * k0.x + q4.y * k0.y + q4.z * k0.z + q4.w * k0.w;
            float p1 = q4.x * k1.x + q4.y * k1.y + q4.z * k1.z + q4.w * k1.w;
            p0 += __shfl_xor_sync(0xFFFFFFFFu, p0, 1);
            p1 += __shfl_xor_sync(0xFFFFFFFFu, p1, 1);
            p0 += __shfl_xor_sync(0xFFFFFFFFu, p0, 2);
            p1 += __shfl_xor_sync(0xFFFFFFFFu, p1, 2);
            float w0 = __expf(p0 * 0.25f);
            float w1 = __expf(p1 * 0.25f);
            if ((lane & 3) == 0) hsum += w0 + w1;
            a.x += w0 * v0.x + w1 * v1.x;
            a.y += w0 * v0.y + w1 * v1.y;
            a.z += w0 * v0.z + w1 * v1.z;
            a.w += w0 * v0.w + w1 * v1.w;
        }
        if (j < end) {
            int c0 = __ldg(&g_ecol[j]);
            uint4 u0 = __ldg(&kv[c0 * 32 + lane]);
            float4 k0 = half4_to_float4(u0.x, u0.y);
            float4 v0 = half4_to_float4(u0.z, u0.w);
            float p0 = q4.x * k0.x + q4.y * k0.y + q4.z * k0.z + q4.w * k0.w;
            p0 += __shfl_xor_sync(0xFFFFFFFFu, p0, 1);
            p0 += __shfl_xor_sync(0xFFFFFFFFu, p0, 2);
            float w0 = __expf(p0 * 0.25f);
            if ((lane & 3) == 0) hsum += w0;
            a.x += w0 * v0.x;
            a.y += w0 * v0.y;
            a.z += w0 * v0.z;
            a.w += w0 * v0.w;
        }
        ((float4*)g_acc)[n * 32 + lane] = a;
    }
    if ((lane & 3) == 0) g_partial[warp * 8 + h] = hsum;
}

// ======================================================================
// Deterministic denominator reduction: 1 block, fixed summation order.
// ======================================================================
__global__ void denom_kernel()
{
    __shared__ float sh[256];
    const int t = threadIdx.x;
    const int h = t & 7;
    const int i0 = t >> 3;
    float s = 0.f;
    for (int i = i0; i < TOTAL_WARPS; i += 32)
        s += g_partial[i * 8 + h];
    sh[t] = s;
    __syncthreads();
    if (t < 8) {
        float tot = 0.f;
        #pragma unroll
        for (int j = 0; j < 32; j++) tot += sh[t + j * 8];
        g_inv_denom[t] = 1.0f / tot;
    }
}

// ======================================================================
// kernel_launch — branch A (convw+QKV) on stream 0; branch B (detect+CSR)
// on side stream; join before gather.
// ======================================================================
extern "C" void kernel_launch(void* const* d_in, const int* in_sizes, int n_in,
                              void* d_out, int out_size)
{
    const float* feat = (const float*)d_in[0];
    const void*  ei   = d_in[1];
    const float* Wq   = (const float*)d_in[2];
    const float* bq   = (const float*)d_in[3];
    const float* Wk   = (const float*)d_in[4];
    const float* bk   = (const float*)d_in[5];
    const float* Wv   = (const float*)d_in[6];
    const float* bv   = (const float*)d_in[7];
    const float* Wo   = (const float*)d_in[8];
    const float* bo   = (const float*)d_in[9];
    float* out = (float*)d_out;

    cudaFuncSetAttribute(gemm_qkv_kernel,
                         cudaFuncAttributeMaxDynamicSharedMemorySize, SM_TOTAL);
    cudaFuncSetAttribute(gemm_mma_kernel,
                         cudaFuncAttributeMaxDynamicSharedMemorySize, SM_TOTAL);

    float* acc;  cudaGetSymbolAddress((void**)&acc,  g_acc);
    float* inv;  cudaGetSymbolAddress((void**)&inv,  g_inv_denom);
    int*   hist; cudaGetSymbolAddress((void**)&hist, g_hist);

    const int gemm_blocks = (NN + 127) / 128;  // 782

    // Side stream + fork/join events (host objects only).
    cudaStream_t s2;
    cudaStreamCreateWithFlags(&s2, cudaStreamNonBlocking);
    cudaEvent_t ev_fork, ev_join;
    cudaEventCreateWithFlags(&ev_fork, cudaEventDisableTiming);
    cudaEventCreateWithFlags(&ev_join, cudaEventDisableTiming);

    // Fork: s2 must be downstream of any prior work on stream 0.
    cudaEventRecord(ev_fork, 0);
    cudaStreamWaitEvent(s2, ev_fork, 0);

    // ---- branch A (stream 0): weight convert + QKV GEMM ----
    convw_kernel<<<64, 256>>>(Wq, Wk, Wv, Wo);
    gemm_qkv_kernel<<<gemm_blocks, 256, SM_TOTAL>>>(feat, bq, bk, bv);

    // ---- branch B (stream s2): dtype detect + CSR build ----
    detect_kernel<<<1, 1, 0, s2>>>((const int*)ei);
    cudaMemsetAsync(hist, 0, NN * sizeof(int), s2);
    count_kernel<<<1280, 256, 0, s2>>>(ei);
    scan1_kernel<<<SCAN_BLOCKS, 256, 0, s2>>>();
    scan2_kernel<<<1, 128, 0, s2>>>();
    scan3_kernel<<<SCAN_BLOCKS, 256, 0, s2>>>();
    fill_kernel<<<1280, 256, 0, s2>>>(ei);
    cudaEventRecord(ev_join, s2);

    // ---- join, then attention + output projection on stream 0 ----
    cudaStreamWaitEvent(0, ev_join, 0);
    gather_kernel<<<GATHER_BLOCKS, GATHER_THREADS>>>();
    denom_kernel<<<1, 256>>>();
    gemm_mma_kernel<<<gemm_blocks, 256, SM_TOTAL>>>(acc, bo, out, inv);
}